// round 5
// baseline (speedup 1.0000x reference)
#include <cuda_runtime.h>

typedef unsigned long long u64;

// Problem constants
#define BB 4
#define CC 32
#define DW 64
#define HH 256
#define WW 256
#define HW 65536

// Scratch (device globals: allocation-free rule)
__device__ float g_t[BB * DW * HW];    // conv1(LN(inp)) output, 64 MB
__device__ float g_xsg[BB * CC * HW];  // gate output, 32 MB
__device__ float g_part[BB * CC * 64]; // per-(b,ch,tile) partial sums
__device__ float g_s[BB * CC];         // SCA scale per (b,ch)

// ---- packed fp32x2 helpers (sm_100+) ----
__device__ __forceinline__ u64 pack2(float lo, float hi) {
    u64 r;
    asm("mov.b64 %0, {%1,%2};" : "=l"(r) : "f"(lo), "f"(hi));
    return r;
}
__device__ __forceinline__ float2 unpack2(u64 v) {
    float lo, hi;
    asm("mov.b64 {%0,%1}, %2;" : "=f"(lo), "=f"(hi) : "l"(v));
    return make_float2(lo, hi);
}
__device__ __forceinline__ u64 ffma2(u64 a, u64 b, u64 c) {
    u64 d;
    asm("fma.rn.f32x2 %0, %1, %2, %3;" : "=l"(d) : "l"(a), "l"(b), "l"(c));
    return d;
}
__device__ __forceinline__ u64 mul2(u64 a, u64 b) {
    u64 d;
    asm("mul.rn.f32x2 %0, %1, %2;" : "=l"(d) : "l"(a), "l"(b));
    return d;
}

// =====================================================================
// K1: LayerNorm(channel) + conv1 (32 -> 64), register-blocked GEMM over
// a 128-pixel tile. Two half-passes of 4 outputs each (low reg peak).
// =====================================================================
__global__ __launch_bounds__(128, 5) void k1(const float* __restrict__ inp,
                                             const float* __restrict__ w1,
                                             const float* __restrict__ b1g,
                                             const float* __restrict__ n1w,
                                             const float* __restrict__ n1b) {
    __shared__ float zs[32 * 128];    // LN output tile
    __shared__ float w1s[32 * 64];    // w1s[k][o]

    int tid = threadIdx.x;
    int bid = blockIdx.x;
    int b = bid >> 9;
    int pix0 = (bid & 511) << 7;

    for (int i = tid; i < 2048; i += 128) {
        int o = i >> 5, k = i & 31;
        w1s[k * 64 + o] = w1[i];
    }

    // per-pixel LayerNorm straight from gmem (coalesced column loads)
    {
        const float* ip = inp + b * CC * HW + pix0 + tid;
        float col[32];
        float s = 0.f, s2 = 0.f;
#pragma unroll
        for (int c = 0; c < 32; c++) {
            col[c] = ip[c * HW];
            s += col[c];
            s2 += col[c] * col[c];
        }
        float mu = s * (1.f / 32.f);
        float var = s2 * (1.f / 32.f) - mu * mu;
        float rstd = rsqrtf(var + 1e-6f);
#pragma unroll
        for (int c = 0; c < 32; c++)
            zs[c * 128 + tid] = (col[c] - mu) * rstd * n1w[c] + n1b[c];
    }
    __syncthreads();

    int tx = tid & 15, tm = tid >> 4;
#pragma unroll
    for (int half = 0; half < 2; half++) {
        int obase = 8 * tm + 4 * half;
        u64 acc[4][4];
#pragma unroll
        for (int j = 0; j < 4; j++) {
            float bv = b1g[obase + j];
#pragma unroll
            for (int q = 0; q < 4; q++) acc[j][q] = pack2(bv, bv);
        }
#pragma unroll
        for (int k = 0; k < 32; k++) {
            float4 wv = *(float4*)&w1s[k * 64 + obase];
            ulonglong2 xa = *(ulonglong2*)&zs[k * 128 + tx * 4];
            ulonglong2 xb = *(ulonglong2*)&zs[k * 128 + 64 + tx * 4];
            u64 xv[4] = {xa.x, xa.y, xb.x, xb.y};
            u64 wd[4] = {pack2(wv.x, wv.x), pack2(wv.y, wv.y),
                         pack2(wv.z, wv.z), pack2(wv.w, wv.w)};
#pragma unroll
            for (int j = 0; j < 4; j++)
#pragma unroll
                for (int q = 0; q < 4; q++)
                    acc[j][q] = ffma2(wd[j], xv[q], acc[j][q]);
        }
#pragma unroll
        for (int j = 0; j < 4; j++) {
            float2 f0 = unpack2(acc[j][0]), f1 = unpack2(acc[j][1]);
            float2 f2 = unpack2(acc[j][2]), f3 = unpack2(acc[j][3]);
            float* op = g_t + (b * DW + obase + j) * HW + pix0 + tx * 4;
            *(float4*)op = make_float4(f0.x, f0.y, f1.x, f1.y);
            *(float4*)(op + 64) = make_float4(f2.x, f2.y, f3.x, f3.y);
        }
    }
}

// =====================================================================
// K2: DDF (bilinear-upsampled per-pixel 3x3 filter) + SimpleGate
//     + per-tile partial channel sums for SCA. (unchanged)
// =====================================================================
__global__ __launch_bounds__(128) void k2(const float* __restrict__ w2g) {
    int tile = blockIdx.x;
    int chp = blockIdx.y;
    int b = blockIdx.z;
    int tyi = tile >> 3, txi = tile & 7;
    int h0 = tyi * 32, w0 = txi * 32;
    const int TSTR = 35;

    __shared__ float tin[2][34 * TSTR];
    __shared__ float Wc[2][9][36];
    __shared__ float red[4];

    int tid = threadIdx.x;

#pragma unroll
    for (int cc = 0; cc < 2; cc++) {
        const float* src = g_t + (b * DW + chp + cc * 32) * HW;
        for (int idx = tid; idx < 34 * 34; idx += 128) {
            int r = idx / 34, c = idx - r * 34;
            int gh = h0 - 1 + r, gw = w0 - 1 + c;
            float v = 0.f;
            if ((unsigned)gh < 256u && (unsigned)gw < 256u) v = src[gh * 256 + gw];
            tin[cc][r * TSTR + c] = v;
        }
    }
    {
        int ybase = 4 * tyi - 1, xbase = 4 * txi - 1;
        for (int idx = tid; idx < 648; idx += 128) {
            int cc = idx / 324;
            int rem = idx - cc * 324;
            int t = rem / 36;
            int rc = rem - t * 36;
            int rr = rc / 6, cj = rc - rr * 6;
            int ys = min(max(ybase + rr, 0), 31);
            int xs = min(max(xbase + cj, 0), 31);
            Wc[cc][t][rc] =
                w2g[(((b * 64 + chp + cc * 32) * 9 + t) * 32 + ys) * 32 + xs];
        }
    }
    __syncthreads();

    int row = tid >> 2;
    int seg = (tid & 3) * 8;
    int h = h0 + row;

    float srcy = (h - 3.5f) * 0.125f;
    float y0f = floorf(srcy);
    float fy = srcy - y0f;
    int y0 = (int)y0f;
    int ybase = 4 * tyi - 1;
    int y0l = max(y0, 0) - ybase;
    int y1l = min(y0 + 1, 31) - ybase;

    int m = 4 * txi + (seg >> 3);
    int xbase = 4 * txi - 1;
    int a0 = max(m - 1, 0) - xbase;
    int a1 = m - xbase;
    int b1i = min(m + 1, 31) - xbase;

    float acc[2][8];
#pragma unroll
    for (int cc = 0; cc < 2; cc++) {
        float ra[10], rb[10], rc[10];
#pragma unroll
        for (int k = 0; k < 10; k++) {
            ra[k] = tin[cc][row * TSTR + seg + k];
            rb[k] = tin[cc][(row + 1) * TSTR + seg + k];
            rc[k] = tin[cc][(row + 2) * TSTR + seg + k];
        }
#pragma unroll
        for (int i = 0; i < 8; i++) acc[cc][i] = 0.f;

#define TAP(RR, T, DX)                                              \
    {                                                               \
        const float* Wp = Wc[cc][T];                                \
        float v0a = Wp[y0l * 6 + a0], v0b = Wp[y1l * 6 + a0];       \
        float v1a = Wp[y0l * 6 + a1], v1b = Wp[y1l * 6 + a1];       \
        float v2a = Wp[y0l * 6 + b1i], v2b = Wp[y1l * 6 + b1i];     \
        float v0 = v0a + fy * (v0b - v0a);                          \
        float v1 = v1a + fy * (v1b - v1a);                          \
        float v2 = v2a + fy * (v2b - v2a);                          \
        float dA = v1 - v0, dB = v2 - v1;                           \
        acc[cc][0] += (v0 + 0.5625f * dA) * RR[0 + DX];             \
        acc[cc][1] += (v0 + 0.6875f * dA) * RR[1 + DX];             \
        acc[cc][2] += (v0 + 0.8125f * dA) * RR[2 + DX];             \
        acc[cc][3] += (v0 + 0.9375f * dA) * RR[3 + DX];             \
        acc[cc][4] += (v1 + 0.0625f * dB) * RR[4 + DX];             \
        acc[cc][5] += (v1 + 0.1875f * dB) * RR[5 + DX];             \
        acc[cc][6] += (v1 + 0.3125f * dB) * RR[6 + DX];             \
        acc[cc][7] += (v1 + 0.4375f * dB) * RR[7 + DX];             \
    }
        TAP(ra, 0, 0) TAP(ra, 1, 1) TAP(ra, 2, 2)
        TAP(rb, 3, 0) TAP(rb, 4, 1) TAP(rb, 5, 2)
        TAP(rc, 6, 0) TAP(rc, 7, 1) TAP(rc, 8, 2)
#undef TAP
    }

    float g[8];
    float tsum = 0.f;
#pragma unroll
    for (int i = 0; i < 8; i++) {
        g[i] = acc[0][i] * acc[1][i];
        tsum += g[i];
    }
    float* op = g_xsg + (b * CC + chp) * HW + h * 256 + w0 + seg;
    *(float4*)(op) = make_float4(g[0], g[1], g[2], g[3]);
    *(float4*)(op + 4) = make_float4(g[4], g[5], g[6], g[7]);

#pragma unroll
    for (int off = 16; off; off >>= 1)
        tsum += __shfl_xor_sync(0xffffffffu, tsum, off);
    if ((tid & 31) == 0) red[tid >> 5] = tsum;
    __syncthreads();
    if (tid == 0)
        g_part[(b * CC + chp) * 64 + tile] = red[0] + red[1] + red[2] + red[3];
}

// =====================================================================
// K3: deterministic reduction of partials + SCA 1x1 conv -> g_s
// =====================================================================
__global__ void k3(const float* __restrict__ sw, const float* __restrict__ sbias) {
    __shared__ float mean_sm[128];
    int tid = threadIdx.x;
    int b = tid >> 5, c = tid & 31;
    float sum = 0.f;
    for (int t = 0; t < 64; t++) sum += g_part[(b * CC + c) * 64 + t];
    mean_sm[tid] = sum * (1.f / 65536.f);
    __syncthreads();
    float acc = sbias[c];
#pragma unroll
    for (int k = 0; k < 32; k++) acc += sw[c * 32 + k] * mean_sm[b * 32 + k];
    g_s[tid] = acc;
}

// =====================================================================
// K4: x*s -> conv3 -> y=inp+beta*x -> LN2 -> conv4 -> gate -> conv5
//     -> out = y + gamma*z. Register-blocked GEMMs, 128-pixel tile.
// Low register peak: y lives in smem only; conv4 split into 2 half-passes;
// gate results buffered in regs, written to xs once conv4 reads finish.
// =====================================================================
__global__ __launch_bounds__(128, 5) void k4(const float* __restrict__ inp,
                                             const float* __restrict__ w3,
                                             const float* __restrict__ b3g,
                                             const float* __restrict__ w4,
                                             const float* __restrict__ b4g,
                                             const float* __restrict__ w5,
                                             const float* __restrict__ b5g,
                                             const float* __restrict__ n2wg,
                                             const float* __restrict__ n2bg,
                                             const float* __restrict__ betag,
                                             const float* __restrict__ gammag,
                                             float* __restrict__ out) {
    __shared__ float xs[32 * 128];   // x tile -> LN2 out -> gate out
    __shared__ float ys[32 * 128];   // y tile (kept until final residual)
    __shared__ float w35s[32 * 32];  // w3 (transposed), restaged with w5
    __shared__ float w4s[32 * 64];   // w4s[k][2p]=w4[p][k], [2p+1]=w4[p+32][k]

    int tid = threadIdx.x;
    int bid = blockIdx.x;
    int b = bid >> 9;
    int pix0 = (bid & 511) << 7;
    int tx = tid & 15, tm = tid >> 4;

    for (int i = tid; i < 1024; i += 128) {
        int c = i >> 5, q = i & 31;
        float s = g_s[b * 32 + c];
        float4 v = *(const float4*)&g_xsg[(b * CC + c) * HW + pix0 + q * 4];
        *(float4*)&xs[c * 128 + q * 4] =
            make_float4(v.x * s, v.y * s, v.z * s, v.w * s);
    }
    for (int i = tid; i < 1024; i += 128) {
        int o = i >> 5, k = i & 31;
        w35s[k * 32 + o] = w3[i];
    }
    for (int i = tid; i < 2048; i += 128) {
        int o = i >> 5, k = i & 31;
        int j = (o < 32) ? 2 * o : 2 * (o - 32) + 1;
        w4s[k * 64 + j] = w4[i];
    }
    __syncthreads();

    // ---- conv3 GEMM (M=32); epilogue: y -> ys (smem only) ----
    {
        u64 acc[4][4];
#pragma unroll
        for (int j = 0; j < 4; j++) {
            float bv = b3g[4 * tm + j];
#pragma unroll
            for (int q = 0; q < 4; q++) acc[j][q] = pack2(bv, bv);
        }
#pragma unroll
        for (int k = 0; k < 32; k++) {
            float4 wv = *(float4*)&w35s[k * 32 + 4 * tm];
            ulonglong2 xa = *(ulonglong2*)&xs[k * 128 + tx * 4];
            ulonglong2 xb = *(ulonglong2*)&xs[k * 128 + 64 + tx * 4];
            u64 xv[4] = {xa.x, xa.y, xb.x, xb.y};
            u64 wd[4] = {pack2(wv.x, wv.x), pack2(wv.y, wv.y),
                         pack2(wv.z, wv.z), pack2(wv.w, wv.w)};
#pragma unroll
            for (int j = 0; j < 4; j++)
#pragma unroll
                for (int q = 0; q < 4; q++)
                    acc[j][q] = ffma2(wd[j], xv[q], acc[j][q]);
        }
#pragma unroll
        for (int j = 0; j < 4; j++) {
            int ch = 4 * tm + j;
            const float* ipc = inp + (b * CC + ch) * HW + pix0 + tx * 4;
            float4 iA = *(const float4*)ipc;
            float4 iB = *(const float4*)(ipc + 64);
            float bt = betag[ch];
            float2 f0 = unpack2(acc[j][0]), f1 = unpack2(acc[j][1]);
            float2 f2 = unpack2(acc[j][2]), f3 = unpack2(acc[j][3]);
            *(float4*)&ys[ch * 128 + tx * 4] =
                make_float4(iA.x + bt * f0.x, iA.y + bt * f0.y,
                            iA.z + bt * f1.x, iA.w + bt * f1.y);
            *(float4*)&ys[ch * 128 + 64 + tx * 4] =
                make_float4(iB.x + bt * f2.x, iB.y + bt * f2.y,
                            iB.z + bt * f3.x, iB.w + bt * f3.y);
        }
    }
    __syncthreads();

    // ---- restage w5; LN2 (ys columns -> xs) ----
    for (int i = tid; i < 1024; i += 128) {
        int o = i >> 5, k = i & 31;
        w35s[k * 32 + o] = w5[i];
    }
    {
        float col[32];
        float s = 0.f, s2 = 0.f;
#pragma unroll
        for (int c = 0; c < 32; c++) {
            col[c] = ys[c * 128 + tid];
            s += col[c];
            s2 += col[c] * col[c];
        }
        float mu = s * (1.f / 32.f);
        float var = s2 * (1.f / 32.f) - mu * mu;
        float rstd = rsqrtf(var + 1e-6f);
#pragma unroll
        for (int c = 0; c < 32; c++)
            xs[c * 128 + tid] = (col[c] - mu) * rstd * n2wg[c] + n2bg[c];
    }
    __syncthreads();

    // ---- conv4 (two half-passes of 2 gate-pairs) + gate in regs ----
    u64 gate[2][2][4];
#pragma unroll
    for (int half = 0; half < 2; half++) {
        u64 alo[2][4], ahi[2][4];
#pragma unroll
        for (int j = 0; j < 2; j++) {
            int p = 4 * tm + 2 * half + j;
            float bl = b4g[p];
            float bh = b4g[p + 32];
#pragma unroll
            for (int q = 0; q < 4; q++) {
                alo[j][q] = pack2(bl, bl);
                ahi[j][q] = pack2(bh, bh);
            }
        }
#pragma unroll
        for (int k = 0; k < 32; k++) {
            float4 w = *(float4*)&w4s[k * 64 + 8 * tm + 4 * half];
            ulonglong2 xa = *(ulonglong2*)&xs[k * 128 + tx * 4];
            ulonglong2 xb = *(ulonglong2*)&xs[k * 128 + 64 + tx * 4];
            u64 xv[4] = {xa.x, xa.y, xb.x, xb.y};
            u64 wl[2] = {pack2(w.x, w.x), pack2(w.z, w.z)};
            u64 wh[2] = {pack2(w.y, w.y), pack2(w.w, w.w)};
#pragma unroll
            for (int j = 0; j < 2; j++)
#pragma unroll
                for (int q = 0; q < 4; q++) {
                    alo[j][q] = ffma2(wl[j], xv[q], alo[j][q]);
                    ahi[j][q] = ffma2(wh[j], xv[q], ahi[j][q]);
                }
        }
#pragma unroll
        for (int j = 0; j < 2; j++)
#pragma unroll
            for (int q = 0; q < 4; q++)
                gate[half][j][q] = mul2(alo[j][q], ahi[j][q]);
    }
    __syncthreads();  // all conv4 reads of xs complete

    // write gate output into xs (conv5 input)
#pragma unroll
    for (int half = 0; half < 2; half++)
#pragma unroll
        for (int j = 0; j < 2; j++) {
            int ch = 4 * tm + 2 * half + j;
            *(ulonglong2*)&xs[ch * 128 + tx * 4] =
                make_ulonglong2(gate[half][j][0], gate[half][j][1]);
            *(ulonglong2*)&xs[ch * 128 + 64 + tx * 4] =
                make_ulonglong2(gate[half][j][2], gate[half][j][3]);
        }
    __syncthreads();

    // ---- conv5 GEMM (M=32) + final residual (y from ys) ----
    {
        u64 acc[4][4];
#pragma unroll
        for (int j = 0; j < 4; j++) {
            float bv = b5g[4 * tm + j];
#pragma unroll
            for (int q = 0; q < 4; q++) acc[j][q] = pack2(bv, bv);
        }
#pragma unroll
        for (int k = 0; k < 32; k++) {
            float4 wv = *(float4*)&w35s[k * 32 + 4 * tm];
            ulonglong2 xa = *(ulonglong2*)&xs[k * 128 + tx * 4];
            ulonglong2 xb = *(ulonglong2*)&xs[k * 128 + 64 + tx * 4];
            u64 xv[4] = {xa.x, xa.y, xb.x, xb.y};
            u64 wd[4] = {pack2(wv.x, wv.x), pack2(wv.y, wv.y),
                         pack2(wv.z, wv.z), pack2(wv.w, wv.w)};
#pragma unroll
            for (int j = 0; j < 4; j++)
#pragma unroll
                for (int q = 0; q < 4; q++)
                    acc[j][q] = ffma2(wd[j], xv[q], acc[j][q]);
        }
#pragma unroll
        for (int j = 0; j < 4; j++) {
            int ch = 4 * tm + j;
            float gm = gammag[ch];
            float4 yA = *(float4*)&ys[ch * 128 + tx * 4];
            float4 yB = *(float4*)&ys[ch * 128 + 64 + tx * 4];
            float2 f0 = unpack2(acc[j][0]), f1 = unpack2(acc[j][1]);
            float2 f2 = unpack2(acc[j][2]), f3 = unpack2(acc[j][3]);
            float* op = out + (b * CC + ch) * HW + pix0 + tx * 4;
            *(float4*)op = make_float4(yA.x + gm * f0.x, yA.y + gm * f0.y,
                                       yA.z + gm * f1.x, yA.w + gm * f1.y);
            *(float4*)(op + 64) =
                make_float4(yB.x + gm * f2.x, yB.y + gm * f2.y,
                            yB.z + gm * f3.x, yB.w + gm * f3.y);
        }
    }
}

extern "C" void kernel_launch(void* const* d_in, const int* in_sizes, int n_in,
                              void* d_out, int out_size) {
    const float* inp     = (const float*)d_in[0];
    const float* w2      = (const float*)d_in[1];
    const float* conv1_w = (const float*)d_in[2];
    const float* conv1_b = (const float*)d_in[3];
    const float* conv3_w = (const float*)d_in[4];
    const float* conv3_b = (const float*)d_in[5];
    const float* sca_w   = (const float*)d_in[6];
    const float* sca_b   = (const float*)d_in[7];
    const float* conv4_w = (const float*)d_in[8];
    const float* conv4_b = (const float*)d_in[9];
    const float* conv5_w = (const float*)d_in[10];
    const float* conv5_b = (const float*)d_in[11];
    const float* norm1_w = (const float*)d_in[12];
    const float* norm1_b = (const float*)d_in[13];
    const float* norm2_w = (const float*)d_in[14];
    const float* norm2_b = (const float*)d_in[15];
    const float* beta    = (const float*)d_in[16];
    const float* gamma   = (const float*)d_in[17];
    float* out = (float*)d_out;

    k1<<<2048, 128>>>(inp, conv1_w, conv1_b, norm1_w, norm1_b);
    k2<<<dim3(64, 32, 4), 128>>>(w2);
    k3<<<1, 128>>>(sca_w, sca_b);
    k4<<<2048, 128>>>(inp, conv3_w, conv3_b, conv4_w, conv4_b, conv5_w, conv5_b,
                      norm2_w, norm2_b, beta, gamma, out);
}

// round 6
// speedup vs baseline: 1.4670x; 1.4670x over previous
#include <cuda_runtime.h>

// Problem constants
#define BB 4
#define CC 32
#define DW 64
#define HH 256
#define WW 256
#define HW 65536

// Scratch (device globals: allocation-free rule)
__device__ float g_t[BB * DW * HW];    // conv1(LN(inp)) output, 64 MB
__device__ float g_xsg[BB * CC * HW];  // gate output, 32 MB
__device__ float g_part[BB * CC * 64]; // per-(b,ch,tile) partial sums
__device__ float g_s[BB * CC];         // SCA scale per (b,ch)

// ---- packed fp32x2 helpers (sm_100+) ----
__device__ __forceinline__ unsigned long long pack2(float lo, float hi) {
    unsigned long long r;
    asm("mov.b64 %0, {%1,%2};" : "=l"(r) : "f"(lo), "f"(hi));
    return r;
}
__device__ __forceinline__ float2 unpack2(unsigned long long v) {
    float lo, hi;
    asm("mov.b64 {%0,%1}, %2;" : "=f"(lo), "=f"(hi) : "l"(v));
    return make_float2(lo, hi);
}
__device__ __forceinline__ unsigned long long ffma2(unsigned long long a,
                                                    unsigned long long b,
                                                    unsigned long long c) {
    unsigned long long d;
    asm("fma.rn.f32x2 %0, %1, %2, %3;" : "=l"(d) : "l"(a), "l"(b), "l"(c));
    return d;
}

// =====================================================================
// K1: per-pixel LayerNorm(channel) + conv1 (32 -> 64), writes g_t
// (R1 version — best known)
// =====================================================================
__global__ __launch_bounds__(128) void k1(const float* __restrict__ inp,
                                          const float* __restrict__ w1,
                                          const float* __restrict__ b1g,
                                          const float* __restrict__ n1w,
                                          const float* __restrict__ n1b) {
    __shared__ unsigned long long wp[32 * 32];  // pairs (w[2o2][c], w[2o2+1][c])
    __shared__ float snw[32], snb[32], sb[64];
    int tid = threadIdx.x;
    for (int i = tid; i < 1024; i += 128) {
        int o2 = i >> 5, c = i & 31;
        wp[i] = pack2(w1[(2 * o2) * 32 + c], w1[(2 * o2 + 1) * 32 + c]);
    }
    if (tid < 32) { snw[tid] = n1w[tid]; snb[tid] = n1b[tid]; }
    if (tid < 64) sb[tid] = b1g[tid];
    __syncthreads();

    int p = blockIdx.x * 128 + tid;
    int b = p >> 16, pix = p & 65535;
    const float* ip = inp + b * CC * HW + pix;

    float x[32];
    float s = 0.f, s2 = 0.f;
#pragma unroll
    for (int c = 0; c < 32; c++) {
        x[c] = ip[c * HW];
        s += x[c];
        s2 += x[c] * x[c];
    }
    float mu = s * (1.f / 32.f);
    float var = s2 * (1.f / 32.f) - mu * mu;
    float rstd = rsqrtf(var + 1e-6f);

    unsigned long long xd[32];
#pragma unroll
    for (int c = 0; c < 32; c++) {
        float v = (x[c] - mu) * rstd * snw[c] + snb[c];
        xd[c] = pack2(v, v);
    }

    float* op = g_t + b * DW * HW + pix;
#pragma unroll
    for (int o2 = 0; o2 < 32; o2++) {
        unsigned long long acc = pack2(sb[2 * o2], sb[2 * o2 + 1]);
#pragma unroll
        for (int c = 0; c < 32; c++) acc = ffma2(wp[o2 * 32 + c], xd[c], acc);
        float2 f = unpack2(acc);
        op[(2 * o2) * HW] = f.x;
        op[(2 * o2 + 1) * HW] = f.y;
    }
}

// =====================================================================
// K2: DDF (bilinear-upsampled per-pixel 3x3 filter) + SimpleGate
//     + per-tile partial channel sums for SCA.
// CHANGED: smem stride 36 (float4-aligned) + vectorized LDS.128 row loads
// (conflict-free: 16B-chunk ids distinct within each quarter-warp).
// =====================================================================
__global__ __launch_bounds__(128) void k2(const float* __restrict__ w2g) {
    int tile = blockIdx.x;  // 0..63
    int chp = blockIdx.y;   // 0..31
    int b = blockIdx.z;
    int tyi = tile >> 3, txi = tile & 7;
    int h0 = tyi * 32, w0 = txi * 32;
    const int TSTR = 36;  // float4-aligned, conflict-free row stride

    __shared__ __align__(16) float tin[2][34 * TSTR];
    __shared__ float Wc[2][9][36];  // [ch][tap][6x6 coarse window]
    __shared__ float red[4];

    int tid = threadIdx.x;

    // stage conv1-output tile + 1-px zero halo, both channels of the pair
#pragma unroll
    for (int cc = 0; cc < 2; cc++) {
        const float* src = g_t + (b * DW + chp + cc * 32) * HW;
        for (int idx = tid; idx < 34 * 34; idx += 128) {
            int r = idx / 34, c = idx - r * 34;
            int gh = h0 - 1 + r, gw = w0 - 1 + c;
            float v = 0.f;
            if ((unsigned)gh < 256u && (unsigned)gw < 256u) v = src[gh * 256 + gw];
            tin[cc][r * TSTR + c] = v;
        }
    }
    // stage the 6x6 coarse-weight window per tap per channel (clamped indices)
    {
        int ybase = 4 * tyi - 1, xbase = 4 * txi - 1;
        for (int idx = tid; idx < 648; idx += 128) {
            int cc = idx / 324;
            int rem = idx - cc * 324;
            int t = rem / 36;
            int rc = rem - t * 36;
            int rr = rc / 6, cj = rc - rr * 6;
            int ys = min(max(ybase + rr, 0), 31);
            int xs = min(max(xbase + cj, 0), 31);
            Wc[cc][t][rc] =
                w2g[(((b * 64 + chp + cc * 32) * 9 + t) * 32 + ys) * 32 + xs];
        }
    }
    __syncthreads();

    int row = tid >> 2;        // 0..31
    int seg = (tid & 3) * 8;   // 0,8,16,24
    int h = h0 + row;

    // y interpolation (uniform per thread); src = (h - 3.5)/8, exact in fp32
    float srcy = (h - 3.5f) * 0.125f;
    float y0f = floorf(srcy);
    float fy = srcy - y0f;
    int y0 = (int)y0f;
    int ybase = 4 * tyi - 1;
    int y0l = max(y0, 0) - ybase;
    int y1l = min(y0 + 1, 31) - ybase;

    int m = 4 * txi + (seg >> 3);
    int xbase = 4 * txi - 1;
    int a0 = max(m - 1, 0) - xbase;
    int a1 = m - xbase;
    int b1i = min(m + 1, 31) - xbase;

    float acc[2][8];
#pragma unroll
    for (int cc = 0; cc < 2; cc++) {
        // vectorized row loads: 3 float4 per row (12 values, use first 10)
        float ra[12], rb[12], rc[12];
        {
            const float* base0 = &tin[cc][row * TSTR + seg];
            const float* base1 = &tin[cc][(row + 1) * TSTR + seg];
            const float* base2 = &tin[cc][(row + 2) * TSTR + seg];
            *(float4*)&ra[0] = *(const float4*)(base0);
            *(float4*)&ra[4] = *(const float4*)(base0 + 4);
            *(float4*)&ra[8] = *(const float4*)(base0 + 8);
            *(float4*)&rb[0] = *(const float4*)(base1);
            *(float4*)&rb[4] = *(const float4*)(base1 + 4);
            *(float4*)&rb[8] = *(const float4*)(base1 + 8);
            *(float4*)&rc[0] = *(const float4*)(base2);
            *(float4*)&rc[4] = *(const float4*)(base2 + 4);
            *(float4*)&rc[8] = *(const float4*)(base2 + 8);
        }
#pragma unroll
        for (int i = 0; i < 8; i++) acc[cc][i] = 0.f;

#define TAP(RR, T, DX)                                              \
    {                                                               \
        const float* Wp = Wc[cc][T];                                \
        float v0a = Wp[y0l * 6 + a0], v0b = Wp[y1l * 6 + a0];       \
        float v1a = Wp[y0l * 6 + a1], v1b = Wp[y1l * 6 + a1];       \
        float v2a = Wp[y0l * 6 + b1i], v2b = Wp[y1l * 6 + b1i];     \
        float v0 = v0a + fy * (v0b - v0a);                          \
        float v1 = v1a + fy * (v1b - v1a);                          \
        float v2 = v2a + fy * (v2b - v2a);                          \
        float dA = v1 - v0, dB = v2 - v1;                           \
        acc[cc][0] += (v0 + 0.5625f * dA) * RR[0 + DX];             \
        acc[cc][1] += (v0 + 0.6875f * dA) * RR[1 + DX];             \
        acc[cc][2] += (v0 + 0.8125f * dA) * RR[2 + DX];             \
        acc[cc][3] += (v0 + 0.9375f * dA) * RR[3 + DX];             \
        acc[cc][4] += (v1 + 0.0625f * dB) * RR[4 + DX];             \
        acc[cc][5] += (v1 + 0.1875f * dB) * RR[5 + DX];             \
        acc[cc][6] += (v1 + 0.3125f * dB) * RR[6 + DX];             \
        acc[cc][7] += (v1 + 0.4375f * dB) * RR[7 + DX];             \
    }
        TAP(ra, 0, 0) TAP(ra, 1, 1) TAP(ra, 2, 2)
        TAP(rb, 3, 0) TAP(rb, 4, 1) TAP(rb, 5, 2)
        TAP(rc, 6, 0) TAP(rc, 7, 1) TAP(rc, 8, 2)
#undef TAP
    }

    // SimpleGate + store + tile-sum
    float g[8];
    float tsum = 0.f;
#pragma unroll
    for (int i = 0; i < 8; i++) {
        g[i] = acc[0][i] * acc[1][i];
        tsum += g[i];
    }
    float* op = g_xsg + (b * CC + chp) * HW + h * 256 + w0 + seg;
    *(float4*)(op) = make_float4(g[0], g[1], g[2], g[3]);
    *(float4*)(op + 4) = make_float4(g[4], g[5], g[6], g[7]);

#pragma unroll
    for (int off = 16; off; off >>= 1)
        tsum += __shfl_xor_sync(0xffffffffu, tsum, off);
    if ((tid & 31) == 0) red[tid >> 5] = tsum;
    __syncthreads();
    if (tid == 0)
        g_part[(b * CC + chp) * 64 + tile] = red[0] + red[1] + red[2] + red[3];
}

// =====================================================================
// K3: deterministic reduction of partials + SCA 1x1 conv -> g_s
// =====================================================================
__global__ void k3(const float* __restrict__ sw, const float* __restrict__ sbias) {
    __shared__ float mean_sm[128];
    int tid = threadIdx.x;  // 128 = 4 batches x 32 channels
    int b = tid >> 5, c = tid & 31;
    float sum = 0.f;
    for (int t = 0; t < 64; t++) sum += g_part[(b * CC + c) * 64 + t];
    mean_sm[tid] = sum * (1.f / 65536.f);
    __syncthreads();
    float acc = sbias[c];
#pragma unroll
    for (int k = 0; k < 32; k++) acc += sw[c * 32 + k] * mean_sm[b * 32 + k];
    g_s[tid] = acc;
}

// =====================================================================
// K4: x*s -> conv3 -> y = inp + beta*x -> LN2 -> conv4 -> gate -> conv5
//     -> out = y + gamma*z  (R1 version — best known)
// =====================================================================
__global__ __launch_bounds__(128) void k4(const float* __restrict__ inp,
                                          const float* __restrict__ w3,
                                          const float* __restrict__ b3g,
                                          const float* __restrict__ w4,
                                          const float* __restrict__ b4g,
                                          const float* __restrict__ w5,
                                          const float* __restrict__ b5g,
                                          const float* __restrict__ n2wg,
                                          const float* __restrict__ n2bg,
                                          const float* __restrict__ betag,
                                          const float* __restrict__ gammag,
                                          float* __restrict__ out) {
    __shared__ unsigned long long w3p[16 * 32];  // pairs (2o2, 2o2+1)
    __shared__ unsigned long long w4p[32 * 32];  // pairs (o, o+32): gate-ready
    __shared__ unsigned long long w5p[16 * 32];
    __shared__ unsigned long long b4p[32];
    __shared__ float sv[32], n2w[32], n2b[32], bet[32], gam[32], b3s[32], b5s[32];

    int tid = threadIdx.x;
    int p = blockIdx.x * 128 + tid;
    int b = p >> 16, pix = p & 65535;

    for (int i = tid; i < 512; i += 128) {
        int o2 = i >> 5, c = i & 31;
        w3p[i] = pack2(w3[(2 * o2) * 32 + c], w3[(2 * o2 + 1) * 32 + c]);
        w5p[i] = pack2(w5[(2 * o2) * 32 + c], w5[(2 * o2 + 1) * 32 + c]);
    }
    for (int i = tid; i < 1024; i += 128) {
        int o = i >> 5, c = i & 31;
        w4p[i] = pack2(w4[o * 32 + c], w4[(o + 32) * 32 + c]);
    }
    if (tid < 32) {
        sv[tid] = g_s[b * 32 + tid];
        n2w[tid] = n2wg[tid];
        n2b[tid] = n2bg[tid];
        bet[tid] = betag[tid];
        gam[tid] = gammag[tid];
        b3s[tid] = b3g[tid];
        b5s[tid] = b5g[tid];
        b4p[tid] = pack2(b4g[tid], b4g[tid + 32]);
    }
    __syncthreads();

    // x = gate_out * s
    unsigned long long xd[32];
#pragma unroll
    for (int c = 0; c < 32; c++) {
        float v = g_xsg[(b * CC + c) * HW + pix] * sv[c];
        xd[c] = pack2(v, v);
    }

    // conv3 + residual with beta
    float y[32];
    const float* ip = inp + b * CC * HW + pix;
#pragma unroll
    for (int o2 = 0; o2 < 16; o2++) {
        unsigned long long acc = pack2(b3s[2 * o2], b3s[2 * o2 + 1]);
#pragma unroll
        for (int c = 0; c < 32; c++) acc = ffma2(w3p[o2 * 32 + c], xd[c], acc);
        float2 f = unpack2(acc);
        y[2 * o2] = ip[(2 * o2) * HW] + bet[2 * o2] * f.x;
        y[2 * o2 + 1] = ip[(2 * o2 + 1) * HW] + bet[2 * o2 + 1] * f.y;
    }

    // LN2
    float s = 0.f, s2 = 0.f;
#pragma unroll
    for (int c = 0; c < 32; c++) {
        s += y[c];
        s2 += y[c] * y[c];
    }
    float mu = s * (1.f / 32.f);
    float var = s2 * (1.f / 32.f) - mu * mu;
    float rstd = rsqrtf(var + 1e-6f);
#pragma unroll
    for (int c = 0; c < 32; c++) {
        float v = (y[c] - mu) * rstd * n2w[c] + n2b[c];
        xd[c] = pack2(v, v);
    }

    // conv4 with (o, o+32) pairing -> gate directly from the f32x2 halves
    float gch[32];
#pragma unroll
    for (int o = 0; o < 32; o++) {
        unsigned long long acc = b4p[o];
#pragma unroll
        for (int c = 0; c < 32; c++) acc = ffma2(w4p[o * 32 + c], xd[c], acc);
        float2 f = unpack2(acc);
        gch[o] = f.x * f.y;
    }
#pragma unroll
    for (int c = 0; c < 32; c++) xd[c] = pack2(gch[c], gch[c]);

    // conv5 + final residual with gamma
    float* op = out + b * CC * HW + pix;
#pragma unroll
    for (int o2 = 0; o2 < 16; o2++) {
        unsigned long long acc = pack2(b5s[2 * o2], b5s[2 * o2 + 1]);
#pragma unroll
        for (int c = 0; c < 32; c++) acc = ffma2(w5p[o2 * 32 + c], xd[c], acc);
        float2 f = unpack2(acc);
        op[(2 * o2) * HW] = y[2 * o2] + gam[2 * o2] * f.x;
        op[(2 * o2 + 1) * HW] = y[2 * o2 + 1] + gam[2 * o2 + 1] * f.y;
    }
}

extern "C" void kernel_launch(void* const* d_in, const int* in_sizes, int n_in,
                              void* d_out, int out_size) {
    const float* inp     = (const float*)d_in[0];
    const float* w2      = (const float*)d_in[1];
    const float* conv1_w = (const float*)d_in[2];
    const float* conv1_b = (const float*)d_in[3];
    const float* conv3_w = (const float*)d_in[4];
    const float* conv3_b = (const float*)d_in[5];
    const float* sca_w   = (const float*)d_in[6];
    const float* sca_b   = (const float*)d_in[7];
    const float* conv4_w = (const float*)d_in[8];
    const float* conv4_b = (const float*)d_in[9];
    const float* conv5_w = (const float*)d_in[10];
    const float* conv5_b = (const float*)d_in[11];
    const float* norm1_w = (const float*)d_in[12];
    const float* norm1_b = (const float*)d_in[13];
    const float* norm2_w = (const float*)d_in[14];
    const float* norm2_b = (const float*)d_in[15];
    const float* beta    = (const float*)d_in[16];
    const float* gamma   = (const float*)d_in[17];
    float* out = (float*)d_out;

    k1<<<2048, 128>>>(inp, conv1_w, conv1_b, norm1_w, norm1_b);
    k2<<<dim3(64, 32, 4), 128>>>(w2);
    k3<<<1, 128>>>(sca_w, sca_b);
    k4<<<2048, 128>>>(inp, conv3_w, conv3_b, conv4_w, conv4_b, conv5_w, conv5_b,
                      norm2_w, norm2_b, beta, gamma, out);
}

// round 7
// speedup vs baseline: 1.5409x; 1.0504x over previous
#include <cuda_runtime.h>
#include <cuda_fp16.h>

// Problem constants
#define BB 4
#define CC 32
#define DW 64
#define HH 256
#define WW 256
#define HW 65536

// Scratch (device globals: allocation-free rule). fp16 intermediates.
__device__ __half g_t[BB * DW * HW];    // conv1(LN(inp)) output, 32 MB
__device__ __half g_xsg[BB * CC * HW];  // gate output, 16 MB
__device__ float g_part[BB * CC * 64];  // per-(b,ch,tile) partial sums
__device__ float g_s[BB * CC];          // SCA scale per (b,ch)

// ---- packed fp32x2 helpers (sm_100+) ----
__device__ __forceinline__ unsigned long long pack2(float lo, float hi) {
    unsigned long long r;
    asm("mov.b64 %0, {%1,%2};" : "=l"(r) : "f"(lo), "f"(hi));
    return r;
}
__device__ __forceinline__ float2 unpack2(unsigned long long v) {
    float lo, hi;
    asm("mov.b64 {%0,%1}, %2;" : "=f"(lo), "=f"(hi) : "l"(v));
    return make_float2(lo, hi);
}
__device__ __forceinline__ unsigned long long ffma2(unsigned long long a,
                                                    unsigned long long b,
                                                    unsigned long long c) {
    unsigned long long d;
    asm("fma.rn.f32x2 %0, %1, %2, %3;" : "=l"(d) : "l"(a), "l"(b), "l"(c));
    return d;
}

// =====================================================================
// K1: per-pixel LayerNorm(channel) + conv1 (32 -> 64), writes g_t (fp16)
// =====================================================================
__global__ __launch_bounds__(128) void k1(const float* __restrict__ inp,
                                          const float* __restrict__ w1,
                                          const float* __restrict__ b1g,
                                          const float* __restrict__ n1w,
                                          const float* __restrict__ n1b) {
    __shared__ unsigned long long wp[32 * 32];  // pairs (w[2o2][c], w[2o2+1][c])
    __shared__ float snw[32], snb[32], sb[64];
    int tid = threadIdx.x;
    for (int i = tid; i < 1024; i += 128) {
        int o2 = i >> 5, c = i & 31;
        wp[i] = pack2(w1[(2 * o2) * 32 + c], w1[(2 * o2 + 1) * 32 + c]);
    }
    if (tid < 32) { snw[tid] = n1w[tid]; snb[tid] = n1b[tid]; }
    if (tid < 64) sb[tid] = b1g[tid];
    __syncthreads();

    int p = blockIdx.x * 128 + tid;
    int b = p >> 16, pix = p & 65535;
    const float* ip = inp + b * CC * HW + pix;

    float x[32];
    float s = 0.f, s2 = 0.f;
#pragma unroll
    for (int c = 0; c < 32; c++) {
        x[c] = ip[c * HW];
        s += x[c];
        s2 += x[c] * x[c];
    }
    float mu = s * (1.f / 32.f);
    float var = s2 * (1.f / 32.f) - mu * mu;
    float rstd = rsqrtf(var + 1e-6f);

    unsigned long long xd[32];
#pragma unroll
    for (int c = 0; c < 32; c++) {
        float v = (x[c] - mu) * rstd * snw[c] + snb[c];
        xd[c] = pack2(v, v);
    }

    __half* op = g_t + b * DW * HW + pix;
#pragma unroll
    for (int o2 = 0; o2 < 32; o2++) {
        unsigned long long acc = pack2(sb[2 * o2], sb[2 * o2 + 1]);
#pragma unroll
        for (int c = 0; c < 32; c++) acc = ffma2(wp[o2 * 32 + c], xd[c], acc);
        float2 f = unpack2(acc);
        op[(2 * o2) * HW] = __float2half_rn(f.x);
        op[(2 * o2 + 1) * HW] = __float2half_rn(f.y);
    }
}

// =====================================================================
// K2: DDF (bilinear-upsampled per-pixel 3x3 filter) + SimpleGate
//     + per-tile partial channel sums for SCA. (R1 structure; fp16 I/O)
// =====================================================================
__global__ __launch_bounds__(128) void k2(const float* __restrict__ w2g) {
    int tile = blockIdx.x;  // 0..63
    int chp = blockIdx.y;   // 0..31
    int b = blockIdx.z;
    int tyi = tile >> 3, txi = tile & 7;
    int h0 = tyi * 32, w0 = txi * 32;
    const int TSTR = 35;  // smem row stride (conflict-free)

    __shared__ float tin[2][34 * TSTR];
    __shared__ float Wc[2][9][36];  // [ch][tap][6x6 coarse window]
    __shared__ float red[4];

    int tid = threadIdx.x;

    // stage conv1-output tile + 1-px zero halo (fp16 -> fp32 in smem)
#pragma unroll
    for (int cc = 0; cc < 2; cc++) {
        const __half* src = g_t + (b * DW + chp + cc * 32) * HW;
        for (int idx = tid; idx < 34 * 34; idx += 128) {
            int r = idx / 34, c = idx - r * 34;
            int gh = h0 - 1 + r, gw = w0 - 1 + c;
            float v = 0.f;
            if ((unsigned)gh < 256u && (unsigned)gw < 256u)
                v = __half2float(src[gh * 256 + gw]);
            tin[cc][r * TSTR + c] = v;
        }
    }
    // stage the 6x6 coarse-weight window per tap per channel (clamped indices)
    {
        int ybase = 4 * tyi - 1, xbase = 4 * txi - 1;
        for (int idx = tid; idx < 648; idx += 128) {
            int cc = idx / 324;
            int rem = idx - cc * 324;
            int t = rem / 36;
            int rc = rem - t * 36;
            int rr = rc / 6, cj = rc - rr * 6;
            int ys = min(max(ybase + rr, 0), 31);
            int xs = min(max(xbase + cj, 0), 31);
            Wc[cc][t][rc] =
                w2g[(((b * 64 + chp + cc * 32) * 9 + t) * 32 + ys) * 32 + xs];
        }
    }
    __syncthreads();

    int row = tid >> 2;        // 0..31
    int seg = (tid & 3) * 8;   // 0,8,16,24
    int h = h0 + row;

    float srcy = (h - 3.5f) * 0.125f;
    float y0f = floorf(srcy);
    float fy = srcy - y0f;
    int y0 = (int)y0f;
    int ybase = 4 * tyi - 1;
    int y0l = max(y0, 0) - ybase;
    int y1l = min(y0 + 1, 31) - ybase;

    int m = 4 * txi + (seg >> 3);
    int xbase = 4 * txi - 1;
    int a0 = max(m - 1, 0) - xbase;
    int a1 = m - xbase;
    int b1i = min(m + 1, 31) - xbase;

    float acc[2][8];
#pragma unroll
    for (int cc = 0; cc < 2; cc++) {
        float ra[10], rb[10], rc[10];
#pragma unroll
        for (int k = 0; k < 10; k++) {
            ra[k] = tin[cc][row * TSTR + seg + k];
            rb[k] = tin[cc][(row + 1) * TSTR + seg + k];
            rc[k] = tin[cc][(row + 2) * TSTR + seg + k];
        }
#pragma unroll
        for (int i = 0; i < 8; i++) acc[cc][i] = 0.f;

#define TAP(RR, T, DX)                                              \
    {                                                               \
        const float* Wp = Wc[cc][T];                                \
        float v0a = Wp[y0l * 6 + a0], v0b = Wp[y1l * 6 + a0];       \
        float v1a = Wp[y0l * 6 + a1], v1b = Wp[y1l * 6 + a1];       \
        float v2a = Wp[y0l * 6 + b1i], v2b = Wp[y1l * 6 + b1i];     \
        float v0 = v0a + fy * (v0b - v0a);                          \
        float v1 = v1a + fy * (v1b - v1a);                          \
        float v2 = v2a + fy * (v2b - v2a);                          \
        float dA = v1 - v0, dB = v2 - v1;                           \
        acc[cc][0] += (v0 + 0.5625f * dA) * RR[0 + DX];             \
        acc[cc][1] += (v0 + 0.6875f * dA) * RR[1 + DX];             \
        acc[cc][2] += (v0 + 0.8125f * dA) * RR[2 + DX];             \
        acc[cc][3] += (v0 + 0.9375f * dA) * RR[3 + DX];             \
        acc[cc][4] += (v1 + 0.0625f * dB) * RR[4 + DX];             \
        acc[cc][5] += (v1 + 0.1875f * dB) * RR[5 + DX];             \
        acc[cc][6] += (v1 + 0.3125f * dB) * RR[6 + DX];             \
        acc[cc][7] += (v1 + 0.4375f * dB) * RR[7 + DX];             \
    }
        TAP(ra, 0, 0) TAP(ra, 1, 1) TAP(ra, 2, 2)
        TAP(rb, 3, 0) TAP(rb, 4, 1) TAP(rb, 5, 2)
        TAP(rc, 6, 0) TAP(rc, 7, 1) TAP(rc, 8, 2)
#undef TAP
    }

    // SimpleGate + fp16 store + tile-sum
    float g[8];
    float tsum = 0.f;
#pragma unroll
    for (int i = 0; i < 8; i++) {
        g[i] = acc[0][i] * acc[1][i];
        tsum += g[i];
    }
    __half2* op =
        (__half2*)(g_xsg + (b * CC + chp) * HW + h * 256 + w0 + seg);
    op[0] = __floats2half2_rn(g[0], g[1]);
    op[1] = __floats2half2_rn(g[2], g[3]);
    op[2] = __floats2half2_rn(g[4], g[5]);
    op[3] = __floats2half2_rn(g[6], g[7]);

#pragma unroll
    for (int off = 16; off; off >>= 1)
        tsum += __shfl_xor_sync(0xffffffffu, tsum, off);
    if ((tid & 31) == 0) red[tid >> 5] = tsum;
    __syncthreads();
    if (tid == 0)
        g_part[(b * CC + chp) * 64 + tile] = red[0] + red[1] + red[2] + red[3];
}

// =====================================================================
// K3: deterministic reduction of partials + SCA 1x1 conv -> g_s
// =====================================================================
__global__ void k3(const float* __restrict__ sw, const float* __restrict__ sbias) {
    __shared__ float mean_sm[128];
    int tid = threadIdx.x;  // 128 = 4 batches x 32 channels
    int b = tid >> 5, c = tid & 31;
    float sum = 0.f;
    for (int t = 0; t < 64; t++) sum += g_part[(b * CC + c) * 64 + t];
    mean_sm[tid] = sum * (1.f / 65536.f);
    __syncthreads();
    float acc = sbias[c];
#pragma unroll
    for (int k = 0; k < 32; k++) acc += sw[c * 32 + k] * mean_sm[b * 32 + k];
    g_s[tid] = acc;
}

// =====================================================================
// K4: x*s -> conv3 -> y = inp + beta*x -> LN2 -> conv4 -> gate -> conv5
//     -> out = y + gamma*z  (R1 structure; fp16 x-load)
// =====================================================================
__global__ __launch_bounds__(128) void k4(const float* __restrict__ inp,
                                          const float* __restrict__ w3,
                                          const float* __restrict__ b3g,
                                          const float* __restrict__ w4,
                                          const float* __restrict__ b4g,
                                          const float* __restrict__ w5,
                                          const float* __restrict__ b5g,
                                          const float* __restrict__ n2wg,
                                          const float* __restrict__ n2bg,
                                          const float* __restrict__ betag,
                                          const float* __restrict__ gammag,
                                          float* __restrict__ out) {
    __shared__ unsigned long long w3p[16 * 32];  // pairs (2o2, 2o2+1)
    __shared__ unsigned long long w4p[32 * 32];  // pairs (o, o+32): gate-ready
    __shared__ unsigned long long w5p[16 * 32];
    __shared__ unsigned long long b4p[32];
    __shared__ float sv[32], n2w[32], n2b[32], bet[32], gam[32], b3s[32], b5s[32];

    int tid = threadIdx.x;
    int p = blockIdx.x * 128 + tid;
    int b = p >> 16, pix = p & 65535;

    for (int i = tid; i < 512; i += 128) {
        int o2 = i >> 5, c = i & 31;
        w3p[i] = pack2(w3[(2 * o2) * 32 + c], w3[(2 * o2 + 1) * 32 + c]);
        w5p[i] = pack2(w5[(2 * o2) * 32 + c], w5[(2 * o2 + 1) * 32 + c]);
    }
    for (int i = tid; i < 1024; i += 128) {
        int o = i >> 5, c = i & 31;
        w4p[i] = pack2(w4[o * 32 + c], w4[(o + 32) * 32 + c]);
    }
    if (tid < 32) {
        sv[tid] = g_s[b * 32 + tid];
        n2w[tid] = n2wg[tid];
        n2b[tid] = n2bg[tid];
        bet[tid] = betag[tid];
        gam[tid] = gammag[tid];
        b3s[tid] = b3g[tid];
        b5s[tid] = b5g[tid];
        b4p[tid] = pack2(b4g[tid], b4g[tid + 32]);
    }
    __syncthreads();

    // x = gate_out * s (fp16 load)
    unsigned long long xd[32];
    const __half* xp = g_xsg + b * CC * HW + pix;
#pragma unroll
    for (int c = 0; c < 32; c++) {
        float v = __half2float(xp[c * HW]) * sv[c];
        xd[c] = pack2(v, v);
    }

    // conv3 + residual with beta
    float y[32];
    const float* ip = inp + b * CC * HW + pix;
#pragma unroll
    for (int o2 = 0; o2 < 16; o2++) {
        unsigned long long acc = pack2(b3s[2 * o2], b3s[2 * o2 + 1]);
#pragma unroll
        for (int c = 0; c < 32; c++) acc = ffma2(w3p[o2 * 32 + c], xd[c], acc);
        float2 f = unpack2(acc);
        y[2 * o2] = ip[(2 * o2) * HW] + bet[2 * o2] * f.x;
        y[2 * o2 + 1] = ip[(2 * o2 + 1) * HW] + bet[2 * o2 + 1] * f.y;
    }

    // LN2
    float s = 0.f, s2 = 0.f;
#pragma unroll
    for (int c = 0; c < 32; c++) {
        s += y[c];
        s2 += y[c] * y[c];
    }
    float mu = s * (1.f / 32.f);
    float var = s2 * (1.f / 32.f) - mu * mu;
    float rstd = rsqrtf(var + 1e-6f);
#pragma unroll
    for (int c = 0; c < 32; c++) {
        float v = (y[c] - mu) * rstd * n2w[c] + n2b[c];
        xd[c] = pack2(v, v);
    }

    // conv4 with (o, o+32) pairing -> gate directly from the f32x2 halves
    float gch[32];
#pragma unroll
    for (int o = 0; o < 32; o++) {
        unsigned long long acc = b4p[o];
#pragma unroll
        for (int c = 0; c < 32; c++) acc = ffma2(w4p[o * 32 + c], xd[c], acc);
        float2 f = unpack2(acc);
        gch[o] = f.x * f.y;
    }
#pragma unroll
    for (int c = 0; c < 32; c++) xd[c] = pack2(gch[c], gch[c]);

    // conv5 + final residual with gamma
    float* op = out + b * CC * HW + pix;
#pragma unroll
    for (int o2 = 0; o2 < 16; o2++) {
        unsigned long long acc = pack2(b5s[2 * o2], b5s[2 * o2 + 1]);
#pragma unroll
        for (int c = 0; c < 32; c++) acc = ffma2(w5p[o2 * 32 + c], xd[c], acc);
        float2 f = unpack2(acc);
        op[(2 * o2) * HW] = y[2 * o2] + gam[2 * o2] * f.x;
        op[(2 * o2 + 1) * HW] = y[2 * o2 + 1] + gam[2 * o2 + 1] * f.y;
    }
}

extern "C" void kernel_launch(void* const* d_in, const int* in_sizes, int n_in,
                              void* d_out, int out_size) {
    const float* inp     = (const float*)d_in[0];
    const float* w2      = (const float*)d_in[1];
    const float* conv1_w = (const float*)d_in[2];
    const float* conv1_b = (const float*)d_in[3];
    const float* conv3_w = (const float*)d_in[4];
    const float* conv3_b = (const float*)d_in[5];
    const float* sca_w   = (const float*)d_in[6];
    const float* sca_b   = (const float*)d_in[7];
    const float* conv4_w = (const float*)d_in[8];
    const float* conv4_b = (const float*)d_in[9];
    const float* conv5_w = (const float*)d_in[10];
    const float* conv5_b = (const float*)d_in[11];
    const float* norm1_w = (const float*)d_in[12];
    const float* norm1_b = (const float*)d_in[13];
    const float* norm2_w = (const float*)d_in[14];
    const float* norm2_b = (const float*)d_in[15];
    const float* beta    = (const float*)d_in[16];
    const float* gamma   = (const float*)d_in[17];
    float* out = (float*)d_out;

    k1<<<2048, 128>>>(inp, conv1_w, conv1_b, norm1_w, norm1_b);
    k2<<<dim3(64, 32, 4), 128>>>(w2);
    k3<<<1, 128>>>(sca_w, sca_b);
    k4<<<2048, 128>>>(inp, conv3_w, conv3_b, conv4_w, conv4_b, conv5_w, conv5_b,
                      norm2_w, norm2_b, beta, gamma, out);
}